// round 5
// baseline (speedup 1.0000x reference)
#include <cuda_runtime.h>
#include <cuda_fp16.h>

#define NN   100000
#define EE   1600000
#define HH   64
#define FIN  14
#define GG   512
#define NBLK 391           // ceil(NN/256)

typedef unsigned long long u64;

// packed f32x2 helpers (Blackwell FFMA2 — only reachable via PTX)
__device__ __forceinline__ u64 fma2(u64 a, u64 b, u64 c) {
    u64 d;
    asm("fma.rn.f32x2 %0, %1, %2, %3;" : "=l"(d) : "l"(a), "l"(b), "l"(c));
    return d;
}
__device__ __forceinline__ u64 dup2(float x) {
    u64 d;
    asm("mov.b64 %0, {%1, %1};" : "=l"(d) : "f"(x));
    return d;
}
__device__ __forceinline__ float2 unpack2(u64 v) {
    float2 r;
    asm("mov.b64 {%0, %1}, %2;" : "=f"(r.x), "=f"(r.y) : "l"(v));
    return r;
}

// ---------------- scratch (device globals) ----------------------------------
__device__ int   g_degc[NN];
__device__ int   g_off[NN + 1];      // CSR offsets by dst
__device__ int   g_cur[NN];          // fill cursors
__device__ int   g_bsum[512];
__device__ float g_dis[NN];          // deg^{-1/2}
__device__ float g_dinv[NN];         // 1/deg
__device__ __align__(16) int2   g_epack[EE];      // (src, norm bits) sorted by dst
__device__ __align__(16) float  g_aggx[NN * FIN];
__device__ __align__(16) __half g_mh[NN * HH];    // fp16 m = h @ W
__device__ __align__(16) float  g_h[NN * HH];
__device__ int   g_gstart[GG + 1];

// ---------------- prep -------------------------------------------------------
__global__ void k_deg(const int* __restrict__ dst) {
    int e = blockIdx.x * blockDim.x + threadIdx.x;
    if (e < EE) atomicAdd(&g_degc[dst[e]], 1);
}

__global__ void k_scanA() {
    __shared__ int s[256];
    int i = blockIdx.x * 256 + threadIdx.x;
    int v = (i < NN) ? g_degc[i] : 0;
    s[threadIdx.x] = v;
    __syncthreads();
    #pragma unroll
    for (int o = 1; o < 256; o <<= 1) {
        int t = (threadIdx.x >= o) ? s[threadIdx.x - o] : 0;
        __syncthreads();
        s[threadIdx.x] += t;
        __syncthreads();
    }
    if (i < NN) g_off[i] = s[threadIdx.x] - v;    // exclusive within block
    if (threadIdx.x == 255) g_bsum[blockIdx.x] = s[255];
}

// offsets (adds block prefix computed in-block) + dinv + graph boundaries
__global__ void k_scanC(const int* __restrict__ batch) {
    __shared__ int red[256];
    int tid = threadIdx.x;
    int partial = 0;
    for (int k = tid; k < blockIdx.x; k += 256) partial += g_bsum[k];
    red[tid] = partial;
    __syncthreads();
    #pragma unroll
    for (int o = 128; o >= 1; o >>= 1) {
        if (tid < o) red[tid] += red[tid + o];
        __syncthreads();
    }
    int bpre = red[0];

    int i = blockIdx.x * 256 + tid;
    if (i >= NN) return;
    int o = g_off[i] + bpre;
    g_off[i] = o;
    g_cur[i] = o;
    float d = (float)(g_degc[i] + 1);
    g_dis[i]  = rsqrtf(d);
    g_dinv[i] = 1.0f / d;
    if (i == 0) g_off[NN] = EE;
    int b = batch[i];
    int pb = (i == 0) ? -1 : batch[i - 1];
    for (int g = pb + 1; g <= b; g++) g_gstart[g] = i;
    if (i == NN - 1)
        for (int g = b + 1; g <= GG; g++) g_gstart[g] = NN;
}

__global__ void k_fill(const int* __restrict__ src, const int* __restrict__ dst) {
    int e = blockIdx.x * blockDim.x + threadIdx.x;
    if (e >= EE) return;
    int s = src[e], d = dst[e];
    float nrm = g_dis[s] * g_dis[d];
    int p = atomicAdd(&g_cur[d], 1);
    g_epack[p] = make_int2(s, __float_as_int(nrm));
}

// ---------------- layer 1: gather-aggregate x (14-wide) then GEMM ----------
__global__ void k_agg14(const float* __restrict__ x) {
    int gidx = blockIdx.x * blockDim.x + threadIdx.x;  // NN*8
    int node = gidx >> 3, c = gidx & 7;
    if (node >= NN) return;
    int beg = g_off[node], end = g_off[node + 1];
    bool act = (c < 7);
    float ax = 0.0f, ay = 0.0f;
    for (int j = beg; j < end; j++) {
        int2 p = g_epack[j];
        float nrm = __int_as_float(p.y);
        if (act) {
            float2 xv = *(const float2*)&x[p.x * FIN + c * 2];
            ax += nrm * xv.x;
            ay += nrm * xv.y;
        }
    }
    if (act) {
        float dv = g_dinv[node];
        float2 xs = *(const float2*)&x[node * FIN + c * 2];
        ax += dv * xs.x;
        ay += dv * xs.y;
        *(float2*)&g_aggx[node * FIN + c * 2] = make_float2(ax, ay);
    }
}

__global__ void k_gemm1(const float* __restrict__ W1, const float* __restrict__ b1) {
    int idx = blockIdx.x * blockDim.x + threadIdx.x;
    if (idx >= NN * HH) return;
    int i = idx >> 6, j = idx & 63;
    float acc = b1[j];
    #pragma unroll
    for (int k = 0; k < FIN; k++)
        acc += g_aggx[i * FIN + k] * W1[k * HH + j];
    g_h[idx] = fmaxf(acc, 0.0f);   // relu applied; h holds relu'ed activations
}

// ---------------- layers 2..5 ------------------------------------------------
// m = h @ W   (h already relu'ed); writes fp16 g_mh; packed-f32x2 FMA mainloop
__global__ void __launch_bounds__(128)
k_gemm64(const float* __restrict__ W) {
    __shared__ float ws[64 * 64];
    __shared__ float hs[64 * 68];    // transposed [k][r], padded
    int tid = threadIdx.x;
    int row0 = blockIdx.x * 64;

    #pragma unroll
    for (int t = 0; t < 32; t++)
        ws[t * 128 + tid] = W[t * 128 + tid];

    #pragma unroll
    for (int t = 0; t < 32; t++) {
        int idx = t * 128 + tid;
        int r = idx >> 6, k = idx & 63;
        int row = row0 + r;
        hs[k * 68 + r] = (row < NN) ? g_h[row * 64 + k] : 0.0f;
    }
    __syncthreads();

    int tx = tid & 7, ty = tid >> 3;          // 8x16 threads, 4 rows x 8 cols each
    u64 acc2[4][4];                            // [row][col-pair], each = 2 fp32
    #pragma unroll
    for (int i = 0; i < 4; i++)
        #pragma unroll
        for (int j = 0; j < 4; j++) acc2[i][j] = 0ull;

    #pragma unroll 8
    for (int k = 0; k < 64; k++) {
        float4 a = *(const float4*)&hs[k * 68 + ty * 4];
        ulonglong2 w01 = *(const ulonglong2*)&ws[k * 64 + tx * 8];
        ulonglong2 w23 = *(const ulonglong2*)&ws[k * 64 + tx * 8 + 4];
        u64 wv[4] = {w01.x, w01.y, w23.x, w23.y};
        u64 a2[4] = {dup2(a.x), dup2(a.y), dup2(a.z), dup2(a.w)};
        #pragma unroll
        for (int i = 0; i < 4; i++)
            #pragma unroll
            for (int j = 0; j < 4; j++)
                acc2[i][j] = fma2(a2[i], wv[j], acc2[i][j]);
    }

    #pragma unroll
    for (int i = 0; i < 4; i++) {
        int row = row0 + ty * 4 + i;
        if (row < NN) {
            uint4 pk;
            float2 p0 = unpack2(acc2[i][0]);
            float2 p1 = unpack2(acc2[i][1]);
            float2 p2 = unpack2(acc2[i][2]);
            float2 p3 = unpack2(acc2[i][3]);
            __half2 h0 = __floats2half2_rn(p0.x, p0.y);
            __half2 h1 = __floats2half2_rn(p1.x, p1.y);
            __half2 h2 = __floats2half2_rn(p2.x, p2.y);
            __half2 h3 = __floats2half2_rn(p3.x, p3.y);
            pk.x = *(unsigned*)&h0; pk.y = *(unsigned*)&h1;
            pk.z = *(unsigned*)&h2; pk.w = *(unsigned*)&h3;
            *(uint4*)&g_mh[row * 64 + tx * 8] = pk;
        }
    }
}

// h = relu( gather(norm * mh[src]) + mh[node]*dinv + b )
// 8 lanes per node, each lane covers 8 columns (16B fp16 per load)
__global__ void __launch_bounds__(256)
k_agg64(const float* __restrict__ b) {
    int t = threadIdx.x;
    int node = blockIdx.x * 32 + (t >> 3);
    int c = t & 7;                    // columns c*8 .. c*8+7
    if (node >= NN) return;
    int beg = g_off[node], end = g_off[node + 1];

    float acc[8];
    #pragma unroll
    for (int i = 0; i < 8; i++) acc[i] = 0.0f;

    int j = beg;
    for (; j + 1 < end; j += 2) {
        int2 p0 = g_epack[j];
        int2 p1 = g_epack[j + 1];
        uint4 r0 = *(const uint4*)&g_mh[p0.x * 64 + c * 8];
        uint4 r1 = *(const uint4*)&g_mh[p1.x * 64 + c * 8];
        float n0 = __int_as_float(p0.y);
        float n1 = __int_as_float(p1.y);
        const unsigned* u0 = &r0.x;
        const unsigned* u1 = &r1.x;
        #pragma unroll
        for (int q = 0; q < 4; q++) {
            float2 a = __half22float2(*(__half2*)&u0[q]);
            float2 bq = __half22float2(*(__half2*)&u1[q]);
            acc[q * 2]     += n0 * a.x + n1 * bq.x;
            acc[q * 2 + 1] += n0 * a.y + n1 * bq.y;
        }
    }
    if (j < end) {
        int2 p = g_epack[j];
        float n = __int_as_float(p.y);
        uint4 r0 = *(const uint4*)&g_mh[p.x * 64 + c * 8];
        const unsigned* u0 = &r0.x;
        #pragma unroll
        for (int q = 0; q < 4; q++) {
            float2 a = __half22float2(*(__half2*)&u0[q]);
            acc[q * 2]     += n * a.x;
            acc[q * 2 + 1] += n * a.y;
        }
    }

    float dv = g_dinv[node];
    uint4 rs = *(const uint4*)&g_mh[node * 64 + c * 8];
    const unsigned* us = &rs.x;
    float4 b0 = *(const float4*)&b[c * 8];
    float4 b1 = *(const float4*)&b[c * 8 + 4];
    float bb[8] = {b0.x, b0.y, b0.z, b0.w, b1.x, b1.y, b1.z, b1.w};
    float o[8];
    #pragma unroll
    for (int q = 0; q < 4; q++) {
        float2 s = __half22float2(*(__half2*)&us[q]);
        o[q * 2]     = fmaxf(acc[q * 2]     + dv * s.x + bb[q * 2],     0.0f);
        o[q * 2 + 1] = fmaxf(acc[q * 2 + 1] + dv * s.y + bb[q * 2 + 1], 0.0f);
    }
    *(float4*)&g_h[node * 64 + c * 8]     = make_float4(o[0], o[1], o[2], o[3]);
    *(float4*)&g_h[node * 64 + c * 8 + 4] = make_float4(o[4], o[5], o[6], o[7]);
}

// ---------------- pooling + head (fused), one block per graph ---------------
__global__ void __launch_bounds__(256)
k_pool(const float* __restrict__ Wl, const float* __restrict__ bl,
       float* __restrict__ out) {
    int g = blockIdx.x;
    int s = g_gstart[g], e = g_gstart[g + 1];
    int tid = threadIdx.x;
    int j = tid & 63, r = tid >> 6;

    float mx = 0.0f;    // relu'ed values >= 0; nonempty graphs -> max >= 0
    for (int i = s + r; i < e; i += 4)
        mx = fmaxf(mx, g_h[i * 64 + j]);

    __shared__ float sm[256];
    sm[tid] = mx;
    __syncthreads();
    if (tid < 64) {
        float p = fmaxf(fmaxf(sm[tid], sm[tid + 64]),
                        fmaxf(sm[tid + 128], sm[tid + 192]));
        sm[tid]      = p * Wl[tid * 2];
        sm[tid + 64] = p * Wl[tid * 2 + 1];
    }
    __syncthreads();
    #pragma unroll
    for (int o = 32; o >= 1; o >>= 1) {
        if (tid < o) {
            sm[tid]      += sm[tid + o];
            sm[tid + 64] += sm[tid + 64 + o];
        }
        __syncthreads();
    }
    if (tid == 0) {
        out[g * 2]     = sm[0]  + bl[0];
        out[g * 2 + 1] = sm[64] + bl[1];
    }
}

// ---------------- launch -----------------------------------------------------
extern "C" void kernel_launch(void* const* d_in, const int* in_sizes, int n_in,
                              void* d_out, int out_size) {
    const float* x  = (const float*)d_in[0];
    const int*   ei = (const int*)d_in[13];
    const int*   bt = (const int*)d_in[14];
    const int* src = ei;
    const int* dst = ei + EE;
    float* out = (float*)d_out;

    void* degc_ptr = nullptr;
    cudaGetSymbolAddress(&degc_ptr, g_degc);
    cudaMemsetAsync(degc_ptr, 0, NN * sizeof(int));

    const int T = 256;
    k_deg  <<<(EE + T - 1) / T, T>>>(dst);
    k_scanA<<<NBLK, T>>>();
    k_scanC<<<NBLK, T>>>(bt);
    k_fill <<<(EE + T - 1) / T, T>>>(src, dst);

    // layer 1
    k_agg14<<<(NN * 8 + T - 1) / T, T>>>(x);
    k_gemm1<<<(NN * HH + T - 1) / T, T>>>((const float*)d_in[1], (const float*)d_in[2]);

    // layers 2..5
    for (int l = 0; l < 4; l++) {
        const float* W = (const float*)d_in[3 + 2 * l];
        const float* b = (const float*)d_in[4 + 2 * l];
        k_gemm64<<<(NN + 63) / 64, 128>>>(W);
        k_agg64 <<<(NN + 31) / 32, 256>>>(b);
    }

    k_pool<<<GG, 256>>>((const float*)d_in[11], (const float*)d_in[12], out);
}

// round 6
// speedup vs baseline: 1.0375x; 1.0375x over previous
#include <cuda_runtime.h>
#include <cuda_fp16.h>

#define NN   100000
#define EE   1600000
#define HH   64
#define FIN  14
#define GG   512
#define NBLK 391           // ceil(NN/256)

typedef unsigned long long u64;

__device__ __forceinline__ u64 fma2(u64 a, u64 b, u64 c) {
    u64 d;
    asm("fma.rn.f32x2 %0, %1, %2, %3;" : "=l"(d) : "l"(a), "l"(b), "l"(c));
    return d;
}
__device__ __forceinline__ u64 dup2(float x) {
    u64 d;
    asm("mov.b64 %0, {%1, %1};" : "=l"(d) : "f"(x));
    return d;
}
__device__ __forceinline__ float2 unpack2(u64 v) {
    float2 r;
    asm("mov.b64 {%0, %1}, %2;" : "=f"(r.x), "=f"(r.y) : "l"(v));
    return r;
}

// ---------------- scratch (device globals) ----------------------------------
__device__ int   g_degc[NN];
__device__ int   g_off[NN + 1];      // CSR offsets by dst
__device__ int   g_cur[NN];          // fill cursors
__device__ int   g_bsum[512];
__device__ float g_dis[NN];          // deg^{-1/2}
__device__ __align__(16) int    g_eidx[EE];       // src index, sorted by dst
__device__ __align__(16) float  g_xs[NN * FIN];   // x * dis[node]
__device__ __align__(16) float  g_aggx[NN * FIN]; // aggregated layer-1 input
__device__ __align__(16) __half g_mh[NN * HH];    // fp16 (h @ W) * dis[row]
__device__ __align__(16) float  g_h[NN * HH];
__device__ int   g_gstart[GG + 1];

// ---------------- prep -------------------------------------------------------
__global__ void k_deg(const int* __restrict__ dst) {
    int e = blockIdx.x * blockDim.x + threadIdx.x;
    if (e < EE) atomicAdd(&g_degc[dst[e]], 1);
}

__global__ void k_scanA() {
    __shared__ int s[256];
    int i = blockIdx.x * 256 + threadIdx.x;
    int v = (i < NN) ? g_degc[i] : 0;
    s[threadIdx.x] = v;
    __syncthreads();
    #pragma unroll
    for (int o = 1; o < 256; o <<= 1) {
        int t = (threadIdx.x >= o) ? s[threadIdx.x - o] : 0;
        __syncthreads();
        s[threadIdx.x] += t;
        __syncthreads();
    }
    if (i < NN) g_off[i] = s[threadIdx.x] - v;    // exclusive within block
    if (threadIdx.x == 255) g_bsum[blockIdx.x] = s[255];
}

// offsets (block prefix in-block) + dis + xs = x*dis + graph boundaries
__global__ void k_scanC(const int* __restrict__ batch, const float* __restrict__ x) {
    __shared__ int red[256];
    int tid = threadIdx.x;
    int partial = 0;
    for (int k = tid; k < blockIdx.x; k += 256) partial += g_bsum[k];
    red[tid] = partial;
    __syncthreads();
    #pragma unroll
    for (int o = 128; o >= 1; o >>= 1) {
        if (tid < o) red[tid] += red[tid + o];
        __syncthreads();
    }
    int bpre = red[0];

    int i = blockIdx.x * 256 + tid;
    if (i >= NN) return;
    int o = g_off[i] + bpre;
    g_off[i] = o;
    g_cur[i] = o;
    float d  = (float)(g_degc[i] + 1);
    float ds = rsqrtf(d);
    g_dis[i] = ds;
    #pragma unroll
    for (int j = 0; j < FIN; j++)
        g_xs[i * FIN + j] = x[i * FIN + j] * ds;
    if (i == 0) g_off[NN] = EE;
    int b = batch[i];
    int pb = (i == 0) ? -1 : batch[i - 1];
    for (int g = pb + 1; g <= b; g++) g_gstart[g] = i;
    if (i == NN - 1)
        for (int g = b + 1; g <= GG; g++) g_gstart[g] = NN;
}

__global__ void k_fill(const int* __restrict__ src, const int* __restrict__ dst) {
    int e = blockIdx.x * blockDim.x + threadIdx.x;
    if (e >= EE) return;
    int s = src[e], d = dst[e];
    int p = atomicAdd(&g_cur[d], 1);
    g_eidx[p] = s;
}

// ---------------- layer 1: aggx = dis_d * (sum xs[src] + xs[node]) ----------
__global__ void k_agg14() {
    int gidx = blockIdx.x * blockDim.x + threadIdx.x;  // NN*8
    int node = gidx >> 3, c = gidx & 7;
    if (node >= NN) return;
    int beg = g_off[node], end = g_off[node + 1];
    bool act = (c < 7);
    float ax = 0.0f, ay = 0.0f;
    for (int j = beg; j < end; j++) {
        int s = g_eidx[j];
        if (act) {
            float2 xv = *(const float2*)&g_xs[s * FIN + c * 2];
            ax += xv.x;
            ay += xv.y;
        }
    }
    if (act) {
        float ds = g_dis[node];
        float2 xs = *(const float2*)&g_xs[node * FIN + c * 2];
        ax = (ax + ds * xs.x) * ds;
        ay = (ay + ds * xs.y) * ds;
        // self term: x*dinv = xs*dis → inside: xs[node]*ds then *ds overall? no:
        // correct form: dis_d*(Σ xs_s) + dinv*x = dis_d*(Σ xs_s + dis_d*x) ... x = xs/ds
        // → dis_d*Σ xs_s + ds*xs = handled above: (ax + ds*xs)*ds gives ds*Σ + ds²*xs = ds*Σ + dinv*x ✓
        *(float2*)&g_aggx[node * FIN + c * 2] = make_float2(ax, ay);
    }
}

__global__ void k_gemm1(const float* __restrict__ W1, const float* __restrict__ b1) {
    int idx = blockIdx.x * blockDim.x + threadIdx.x;
    if (idx >= NN * HH) return;
    int i = idx >> 6, j = idx & 63;
    float acc = b1[j];
    #pragma unroll
    for (int k = 0; k < FIN; k++)
        acc += g_aggx[i * FIN + k] * W1[k * HH + j];
    g_h[idx] = fmaxf(acc, 0.0f);
}

// ---------------- layers 2..5 ------------------------------------------------
// mh = (h @ W) * dis[row]  (fp16)
__global__ void __launch_bounds__(128)
k_gemm64(const float* __restrict__ W) {
    __shared__ float ws[64 * 64];
    __shared__ float hs[64 * 68];
    int tid = threadIdx.x;
    int row0 = blockIdx.x * 64;

    #pragma unroll
    for (int t = 0; t < 32; t++)
        ws[t * 128 + tid] = W[t * 128 + tid];

    #pragma unroll
    for (int t = 0; t < 32; t++) {
        int idx = t * 128 + tid;
        int r = idx >> 6, k = idx & 63;
        int row = row0 + r;
        hs[k * 68 + r] = (row < NN) ? g_h[row * 64 + k] : 0.0f;
    }
    __syncthreads();

    int tx = tid & 7, ty = tid >> 3;
    u64 acc2[4][4];
    #pragma unroll
    for (int i = 0; i < 4; i++)
        #pragma unroll
        for (int j = 0; j < 4; j++) acc2[i][j] = 0ull;

    #pragma unroll 8
    for (int k = 0; k < 64; k++) {
        float4 a = *(const float4*)&hs[k * 68 + ty * 4];
        ulonglong2 w01 = *(const ulonglong2*)&ws[k * 64 + tx * 8];
        ulonglong2 w23 = *(const ulonglong2*)&ws[k * 64 + tx * 8 + 4];
        u64 wv[4] = {w01.x, w01.y, w23.x, w23.y};
        u64 a2[4] = {dup2(a.x), dup2(a.y), dup2(a.z), dup2(a.w)};
        #pragma unroll
        for (int i = 0; i < 4; i++)
            #pragma unroll
            for (int j = 0; j < 4; j++)
                acc2[i][j] = fma2(a2[i], wv[j], acc2[i][j]);
    }

    #pragma unroll
    for (int i = 0; i < 4; i++) {
        int row = row0 + ty * 4 + i;
        if (row < NN) {
            float ds = g_dis[row];
            uint4 pk;
            float2 p0 = unpack2(acc2[i][0]);
            float2 p1 = unpack2(acc2[i][1]);
            float2 p2 = unpack2(acc2[i][2]);
            float2 p3 = unpack2(acc2[i][3]);
            __half2 h0 = __floats2half2_rn(p0.x * ds, p0.y * ds);
            __half2 h1 = __floats2half2_rn(p1.x * ds, p1.y * ds);
            __half2 h2 = __floats2half2_rn(p2.x * ds, p2.y * ds);
            __half2 h3 = __floats2half2_rn(p3.x * ds, p3.y * ds);
            pk.x = *(unsigned*)&h0; pk.y = *(unsigned*)&h1;
            pk.z = *(unsigned*)&h2; pk.w = *(unsigned*)&h3;
            *(uint4*)&g_mh[row * 64 + tx * 8] = pk;
        }
    }
}

// h = relu( dis_d * (sum mh[src] + dis_d*mh[node]... ) wait:
//   m_d*dinv = mh_d*dis_d ; Σ dis_s dis_d m_s = dis_d Σ mh_s
//   h = relu( dis_d*(Σ mh_s + mh_d) + b )
// 8 lanes per node, 8 cols each (16B fp16 per load); edge loop is pure adds
__global__ void __launch_bounds__(256)
k_agg64(const float* __restrict__ b) {
    int t = threadIdx.x;
    int node = blockIdx.x * 32 + (t >> 3);
    int c = t & 7;
    if (node >= NN) return;
    int beg = g_off[node], end = g_off[node + 1];

    float acc[8];
    #pragma unroll
    for (int i = 0; i < 8; i++) acc[i] = 0.0f;

    int j = beg;
    for (; j + 1 < end; j += 2) {
        int s0 = g_eidx[j];
        int s1 = g_eidx[j + 1];
        uint4 r0 = *(const uint4*)&g_mh[s0 * 64 + c * 8];
        uint4 r1 = *(const uint4*)&g_mh[s1 * 64 + c * 8];
        const unsigned* u0 = &r0.x;
        const unsigned* u1 = &r1.x;
        #pragma unroll
        for (int q = 0; q < 4; q++) {
            float2 a  = __half22float2(*(__half2*)&u0[q]);
            float2 bq = __half22float2(*(__half2*)&u1[q]);
            acc[q * 2]     += a.x + bq.x;
            acc[q * 2 + 1] += a.y + bq.y;
        }
    }
    if (j < end) {
        int s = g_eidx[j];
        uint4 r0 = *(const uint4*)&g_mh[s * 64 + c * 8];
        const unsigned* u0 = &r0.x;
        #pragma unroll
        for (int q = 0; q < 4; q++) {
            float2 a = __half22float2(*(__half2*)&u0[q]);
            acc[q * 2]     += a.x;
            acc[q * 2 + 1] += a.y;
        }
    }

    float ds = g_dis[node];
    uint4 rs = *(const uint4*)&g_mh[node * 64 + c * 8];
    const unsigned* us = &rs.x;
    float4 b0 = *(const float4*)&b[c * 8];
    float4 b1 = *(const float4*)&b[c * 8 + 4];
    float bb[8] = {b0.x, b0.y, b0.z, b0.w, b1.x, b1.y, b1.z, b1.w};
    float o[8];
    #pragma unroll
    for (int q = 0; q < 4; q++) {
        float2 s2 = __half22float2(*(__half2*)&us[q]);
        o[q * 2]     = fmaxf(ds * (acc[q * 2]     + s2.x) + bb[q * 2],     0.0f);
        o[q * 2 + 1] = fmaxf(ds * (acc[q * 2 + 1] + s2.y) + bb[q * 2 + 1], 0.0f);
    }
    *(float4*)&g_h[node * 64 + c * 8]     = make_float4(o[0], o[1], o[2], o[3]);
    *(float4*)&g_h[node * 64 + c * 8 + 4] = make_float4(o[4], o[5], o[6], o[7]);
}

// ---------------- pooling + head (fused), one block per graph ---------------
__global__ void __launch_bounds__(256)
k_pool(const float* __restrict__ Wl, const float* __restrict__ bl,
       float* __restrict__ out) {
    int g = blockIdx.x;
    int s = g_gstart[g], e = g_gstart[g + 1];
    int tid = threadIdx.x;
    int j = tid & 63, r = tid >> 6;

    float mx = 0.0f;
    for (int i = s + r; i < e; i += 4)
        mx = fmaxf(mx, g_h[i * 64 + j]);

    __shared__ float sm[256];
    sm[tid] = mx;
    __syncthreads();
    if (tid < 64) {
        float p = fmaxf(fmaxf(sm[tid], sm[tid + 64]),
                        fmaxf(sm[tid + 128], sm[tid + 192]));
        sm[tid]      = p * Wl[tid * 2];
        sm[tid + 64] = p * Wl[tid * 2 + 1];
    }
    __syncthreads();
    #pragma unroll
    for (int o = 32; o >= 1; o >>= 1) {
        if (tid < o) {
            sm[tid]      += sm[tid + o];
            sm[tid + 64] += sm[tid + 64 + o];
        }
        __syncthreads();
    }
    if (tid == 0) {
        out[g * 2]     = sm[0]  + bl[0];
        out[g * 2 + 1] = sm[64] + bl[1];
    }
}

// ---------------- launch -----------------------------------------------------
extern "C" void kernel_launch(void* const* d_in, const int* in_sizes, int n_in,
                              void* d_out, int out_size) {
    const float* x  = (const float*)d_in[0];
    const int*   ei = (const int*)d_in[13];
    const int*   bt = (const int*)d_in[14];
    const int* src = ei;
    const int* dst = ei + EE;
    float* out = (float*)d_out;

    void* degc_ptr = nullptr;
    cudaGetSymbolAddress(&degc_ptr, g_degc);
    cudaMemsetAsync(degc_ptr, 0, NN * sizeof(int));

    const int T = 256;
    k_deg  <<<(EE + T - 1) / T, T>>>(dst);
    k_scanA<<<NBLK, T>>>();
    k_scanC<<<NBLK, T>>>(bt, x);
    k_fill <<<(EE + T - 1) / T, T>>>(src, dst);

    // layer 1
    k_agg14<<<(NN * 8 + T - 1) / T, T>>>();
    k_gemm1<<<(NN * HH + T - 1) / T, T>>>((const float*)d_in[1], (const float*)d_in[2]);

    // layers 2..5
    for (int l = 0; l < 4; l++) {
        const float* W = (const float*)d_in[3 + 2 * l];
        const float* b = (const float*)d_in[4 + 2 * l];
        k_gemm64<<<(NN + 63) / 64, 128>>>(W);
        k_agg64 <<<(NN + 31) / 32, 256>>>(b);
    }

    k_pool<<<GG, 256>>>((const float*)d_in[11], (const float*)d_in[12], out);
}